// round 12
// baseline (speedup 1.0000x reference)
#include <cuda_runtime.h>
#include <math.h>
#include <cstdint>

#define NN   65536
#define DD   128
#define EE   524288
#define BB   128
#define NPER 512
#define SLOTS 64

// ---------------- scratch (device globals; no allocs allowed) ----------------
__device__ int   g_cnt[NN];            // edge count per dst (slot allocator); reset by k_mlp
__device__ int   g_deg[NN];            // active-neighbor count (layers >= 1, from pool)
__device__ int   g_csr[NN * SLOTS];    // fixed-slot CSR: src ids at dst*SLOTS+j
__device__ float g_x[NN * DD];         // node features after pool (layers >= 1)
__device__ uint32_t g_mH[NN * 64];     // mean hi (packed bf16x2)
__device__ uint32_t g_mL[NN * 64];     // mean lo
__device__ uint32_t g_wH[6][128 * 64]; // weights hi: [layer*2 + (0=wl,1=wr)]
__device__ uint32_t g_wL[6][128 * 64]; // weights lo
__device__ float g_h[NN * DD];         // SAGE output (pre-pool), fp32
__device__ unsigned char g_nm[NN];     // node mask
__device__ float g_z[BB * 256];        // summed readouts

// ---------------- helpers ----------------
__device__ __forceinline__ uint32_t pack_bf16x2(float v0, float v1) {
    uint32_t r;
    asm("cvt.rn.bf16x2.f32 %0, %1, %2;" : "=r"(r) : "f"(v1), "f"(v0));
    return r;
}
__device__ __forceinline__ float bf_lo(uint32_t u) { return __uint_as_float(u << 16); }
__device__ __forceinline__ float bf_hi(uint32_t u) { return __uint_as_float(u & 0xFFFF0000u); }

__device__ __forceinline__ void split4(float4 v, uint32_t* h, uint32_t* l) {
    h[0] = pack_bf16x2(v.x, v.y);
    l[0] = pack_bf16x2(v.x - bf_lo(h[0]), v.y - bf_hi(h[0]));
    h[1] = pack_bf16x2(v.z, v.w);
    l[1] = pack_bf16x2(v.z - bf_lo(h[1]), v.w - bf_hi(h[1]));
}

__device__ __forceinline__ void mma_bf16(float* c,
    uint32_t a0, uint32_t a1, uint32_t a2, uint32_t a3,
    uint32_t b0, uint32_t b1)
{
    asm volatile(
        "mma.sync.aligned.m16n8k16.row.col.f32.bf16.bf16.f32 "
        "{%0,%1,%2,%3},{%4,%5,%6,%7},{%8,%9},{%0,%1,%2,%3};"
        : "+f"(c[0]), "+f"(c[1]), "+f"(c[2]), "+f"(c[3])
        : "r"(a0), "r"(a1), "r"(a2), "r"(a3), "r"(b0), "r"(b1));
}

__device__ __forceinline__ void ldm_x4(uint32_t* r, uint32_t addr) {
    asm volatile("ldmatrix.sync.aligned.m8n8.x4.shared.b16 {%0,%1,%2,%3}, [%4];"
        : "=r"(r[0]), "=r"(r[1]), "=r"(r[2]), "=r"(r[3]) : "r"(addr));
}

__device__ __forceinline__ uint32_t smem_u32(const void* p) {
    uint32_t a;
    asm("{ .reg .u64 t; cvta.to.shared.u64 t, %1; cvt.u32.u64 %0, t; }" : "=r"(a) : "l"(p));
    return a;
}
__device__ __forceinline__ void cp16(uint32_t saddr, const void* gaddr) {
    asm volatile("cp.async.cg.shared.global [%0], [%1], 16;" :: "r"(saddr), "l"(gaddr) : "memory");
}
#define CP_COMMIT() asm volatile("cp.async.commit_group;" ::: "memory")
#define CP_WAIT1()  asm volatile("cp.async.wait_group 1;" ::: "memory")
#define CP_WAIT0()  asm volatile("cp.async.wait_group 0;" ::: "memory")

// ---------------- init: weight splits, mask, z, fixed-slot CSR build --------
// g_cnt is zero on entry (static init first run; k_mlp re-zeroes for replays).
__global__ void k_init(const int* __restrict__ ei,
                       const float* w0, const float* w1, const float* w2,
                       const float* w3, const float* w4, const float* w5) {
    int i = blockIdx.x * blockDim.x + threadIdx.x;   // exactly EE threads
    if (i < NN) g_nm[i] = 1;
    if (i < BB * 256) g_z[i] = 0.f;
    if (i < 6 * 8192) {
        int m = i >> 13, j = i & 8191;
        const float* wp = (m == 0) ? w0 : (m == 1) ? w1 : (m == 2) ? w2
                         : (m == 3) ? w3 : (m == 4) ? w4 : w5;
        float2 w = reinterpret_cast<const float2*>(wp)[j];
        uint32_t wh = pack_bf16x2(w.x, w.y);
        uint32_t wl2 = pack_bf16x2(w.x - bf_lo(wh), w.y - bf_hi(wh));
        g_wH[m][j] = wh;
        g_wL[m][j] = wl2;
    }
    int dst = ei[EE + i];
    int src = ei[i];
    int pos = atomicAdd(&g_cnt[dst], 1);
    if (pos < SLOTS) g_csr[dst * SLOTS + pos] = src;
}

// ---------------- neighbor mean: fixed-slot fp32 gather ----------------
// deg: layer 0 -> g_cnt (all active); layers >= 1 -> g_deg (from pool)
__global__ void k_aggregate(const float* __restrict__ xsrc, int use_cnt_deg) {
    int node = blockIdx.x * 8 + (threadIdx.x >> 5);
    int lane = threadIdx.x & 31;
    uint2* MH = reinterpret_cast<uint2*>(g_mH);
    uint2* ML = reinterpret_cast<uint2*>(g_mL);
    if (!g_nm[node]) {
        MH[node * 32 + lane] = make_uint2(0u, 0u);
        ML[node * 32 + lane] = make_uint2(0u, 0u);
        return;
    }
    int cnt = g_cnt[node];
    const int* row = g_csr + node * SLOTS;
    const float4* X = reinterpret_cast<const float4*>(xsrc);
    float a0 = 0.f, a1 = 0.f, a2 = 0.f, a3 = 0.f;
#pragma unroll 4
    for (int j = 0; j < cnt; j++) {
        int s = row[j];
        float4 v = X[(size_t)s * 32 + lane]; // masked rows are all-zero
        a0 += v.x; a1 += v.y; a2 += v.z; a3 += v.w;
    }
    int dg = use_cnt_deg ? cnt : g_deg[node];
    float inv = 1.f / (float)(dg > 1 ? dg : 1);
    a0 *= inv; a1 *= inv; a2 *= inv; a3 *= inv;
    uint32_t h0 = pack_bf16x2(a0, a1);
    uint32_t h1 = pack_bf16x2(a2, a3);
    uint32_t l0 = pack_bf16x2(a0 - bf_lo(h0), a1 - bf_hi(h0));
    uint32_t l1 = pack_bf16x2(a2 - bf_lo(h1), a3 - bf_hi(h1));
    MH[node * 32 + lane] = make_uint2(h0, h1);
    ML[node * 32 + lane] = make_uint2(l0, l1);
}

// ---------------- 3xBF16 GEMM: mean via cp.async, x via LDG+inline split ----
#define BUF_U32   2560          // 128*20
#define STG_U32   10240         // 4 buffers
#define SMEM_GEMM 81920

__global__ __launch_bounds__(256, 2) void k_gemm(int layer, const float* __restrict__ bl,
                                                 const float* __restrict__ xsrc)
{
    extern __shared__ __align__(16) uint32_t dsm[];
    __shared__ float sbias[128];
    uint32_t sb0 = smem_u32(dsm);

    int t = threadIdx.x;
    int lane = t & 31;
    int g = lane >> 2;      // 0..7
    int tq = lane & 3;      // 0..3
    int warp = t >> 5;
    int wm = warp >> 1;     // 0..3
    int wn = warp & 1;      // 0..1
    int base = blockIdx.x * 128;
    size_t bofs = (size_t)base * 64;

    if (t < 128) sbias[t] = bl[t];

    int r0c = t >> 2, q4c = (t & 3) * 4;
    int r1c = r0c + 64;

    int q = lane >> 3;
    int lr = lane & 7;
    int a_row0 = wm * 32 + (q & 1) * 8 + lr;
    int a_coladd = (q >> 1) * 4;
    int b_row0 = wn * 64 + (q >> 1) * 8 + lr;
    int b_coladd = (q & 1) * 4;

    float acc[2][8][4];
#pragma unroll
    for (int mt = 0; mt < 2; mt++)
#pragma unroll
        for (int nt = 0; nt < 8; nt++)
#pragma unroll
            for (int i = 0; i < 4; i++) acc[mt][nt][i] = 0.f;

    auto issue = [&](int c, int st) {
        const uint32_t* wH = g_wH[(layer << 1) | (c >> 2)] + (c & 3) * 16;
        const uint32_t* wLp = g_wL[(layer << 1) | (c >> 2)] + (c & 3) * 16;
        uint32_t sb = sb0 + st * (STG_U32 * 4);
        if (c < 4) {
            const uint32_t* aH = g_mH + bofs + c * 16;
            const uint32_t* aL = g_mL + bofs + c * 16;
            cp16(sb + (r0c * 20 + q4c) * 4,           aH + (size_t)r0c * 64 + q4c);
            cp16(sb + (r1c * 20 + q4c) * 4,           aH + (size_t)r1c * 64 + q4c);
            cp16(sb + (BUF_U32 + r0c * 20 + q4c) * 4, aL + (size_t)r0c * 64 + q4c);
            cp16(sb + (BUF_U32 + r1c * 20 + q4c) * 4, aL + (size_t)r1c * 64 + q4c);
        }
        cp16(sb + (2 * BUF_U32 + r0c * 20 + q4c) * 4, wH + (size_t)r0c * 64 + q4c);
        cp16(sb + (2 * BUF_U32 + r1c * 20 + q4c) * 4, wH + (size_t)r1c * 64 + q4c);
        cp16(sb + (3 * BUF_U32 + r0c * 20 + q4c) * 4, wLp + (size_t)r0c * 64 + q4c);
        cp16(sb + (3 * BUF_U32 + r1c * 20 + q4c) * 4, wLp + (size_t)r1c * 64 + q4c);
        CP_COMMIT();
    };

    float4 xv[4];
    auto ldx = [&](int c) {   // c in 4..7
        const float4* X4 = reinterpret_cast<const float4*>(xsrc) + (size_t)base * 32 + (c - 4) * 8;
#pragma unroll
        for (int j = 0; j < 4; j++) {
            int idx = t + j * 256;
            int row = idx >> 3, qq = idx & 7;
            xv[j] = X4[(size_t)row * 32 + qq];
        }
    };
    auto stx = [&](int st) {
        uint32_t* dH = dsm + st * STG_U32;
        uint32_t* dL = dH + BUF_U32;
#pragma unroll
        for (int j = 0; j < 4; j++) {
            int idx = t + j * 256;
            int row = idx >> 3, qq = idx & 7;
            uint32_t h[2], l[2];
            split4(xv[j], h, l);
            *reinterpret_cast<uint2*>(dH + row * 20 + qq * 2) = make_uint2(h[0], h[1]);
            *reinterpret_cast<uint2*>(dL + row * 20 + qq * 2) = make_uint2(l[0], l[1]);
        }
    };

    issue(0, 0);
    for (int c = 0; c < 8; c++) {
        int st = c & 1;
        if (c < 7) {
            issue(c + 1, st ^ 1);
            if (c + 1 >= 4) ldx(c + 1);
            CP_WAIT1();
        } else {
            CP_WAIT0();
        }
        __syncthreads();

        uint32_t bA_H = sb0 + st * (STG_U32 * 4);
        uint32_t bA_L = bA_H + BUF_U32 * 4;
        uint32_t bW_H = bA_H + 2 * BUF_U32 * 4;
        uint32_t bW_L = bA_H + 3 * BUF_U32 * 4;

#pragma unroll
        for (int ks = 0; ks < 2; ks++) {
            int cb = ks * 8;
            uint32_t aH[2][4], aL[2][4];
#pragma unroll
            for (int mt = 0; mt < 2; mt++) {
                uint32_t ar = ((uint32_t)((a_row0 + mt * 16) * 20 + cb + a_coladd)) * 4;
                ldm_x4(aH[mt], bA_H + ar);
                ldm_x4(aL[mt], bA_L + ar);
            }
#pragma unroll
            for (int half = 0; half < 2; half++) {
                uint32_t bh[8], blo[8];
#pragma unroll
                for (int j2 = 0; j2 < 2; j2++) {
                    uint32_t br = ((uint32_t)((b_row0 + half * 32 + j2 * 16) * 20 + cb + b_coladd)) * 4;
                    ldm_x4(&bh[j2 * 4],  bW_H + br);
                    ldm_x4(&blo[j2 * 4], bW_L + br);
                }
#pragma unroll
                for (int nt2 = 0; nt2 < 4; nt2++) {
                    int nt = half * 4 + nt2;
                    uint32_t b0h = bh[nt2 * 2], b1h = bh[nt2 * 2 + 1];
                    uint32_t b0l = blo[nt2 * 2], b1l = blo[nt2 * 2 + 1];
#pragma unroll
                    for (int mt = 0; mt < 2; mt++) {
                        mma_bf16(acc[mt][nt], aH[mt][0], aH[mt][1], aH[mt][2], aH[mt][3], b0h, b1h);
                        mma_bf16(acc[mt][nt], aH[mt][0], aH[mt][1], aH[mt][2], aH[mt][3], b0l, b1l);
                        mma_bf16(acc[mt][nt], aL[mt][0], aL[mt][1], aL[mt][2], aL[mt][3], b0h, b1h);
                    }
                }
            }
        }

        if (c < 7 && c + 1 >= 4) stx(st ^ 1);
        __syncthreads();
    }

#pragma unroll
    for (int nt = 0; nt < 8; nt++) {
        int col = wn * 64 + nt * 8 + tq * 2;
        float bb0 = sbias[col];
        float bb1 = sbias[col + 1];
#pragma unroll
        for (int mt = 0; mt < 2; mt++) {
            int r = base + wm * 32 + mt * 16 + g;
            float2 o;
            o.x = fmaxf(acc[mt][nt][0] + bb0, 0.f);
            o.y = fmaxf(acc[mt][nt][1] + bb1, 0.f);
            *reinterpret_cast<float2*>(&g_h[(size_t)r * 128 + col]) = o;
            o.x = fmaxf(acc[mt][nt][2] + bb0, 0.f);
            o.y = fmaxf(acc[mt][nt][3] + bb1, 0.f);
            *reinterpret_cast<float2*>(&g_h[(size_t)(r + 8) * 128 + col]) = o;
        }
    }
}

// ---------------- top-k pool + readout + fp32 x output + next-layer deg -----
__global__ __launch_bounds__(512) void k_pool(const float* __restrict__ pw, int k, float kf) {
    int g = blockIdx.x;
    int tid = threadIdx.x;

    __shared__ float w[128];
    __shared__ float scr[512];
    __shared__ float srt[512];
    __shared__ float fac[512];
    __shared__ unsigned char sel[512];
    __shared__ float smx[8][128];
    __shared__ float ssm[8][128];
    __shared__ float inv_norm;
    __shared__ int cgt;

    if (tid < 128) w[tid] = pw[tid];
    if (tid == 0) cgt = 0;
    __syncthreads();
    if (tid == 0) {
        float s = 0.f;
        for (int i = 0; i < 128; i++) s += w[i] * w[i];
        inv_norm = 1.f / (sqrtf(s) + 1e-16f);
    }
    __syncthreads();

    int wid = tid >> 5, lane = tid & 31;
    for (int n = wid; n < 512; n += 16) {
        int node = g * 512 + n;
        float4 p = reinterpret_cast<const float4*>(g_h + (size_t)node * 128)[lane];
        float4 ww = reinterpret_cast<const float4*>(w)[lane];
        float d = p.x * ww.x + p.y * ww.y + p.z * ww.z + p.w * ww.w;
#pragma unroll
        for (int off = 16; off > 0; off >>= 1)
            d += __shfl_xor_sync(0xffffffffu, d, off);
        if (lane == 0)
            scr[n] = g_nm[node] ? d * inv_norm : -INFINITY;
    }
    __syncthreads();
    srt[tid] = scr[tid];
    __syncthreads();

    for (int kk = 2; kk <= 512; kk <<= 1) {
        for (int j = kk >> 1; j > 0; j >>= 1) {
            int ixj = tid ^ j;
            if (ixj > tid) {
                float a = srt[tid], b = srt[ixj];
                bool asc = ((tid & kk) == 0);
                if ((a > b) == asc) { srt[tid] = b; srt[ixj] = a; }
            }
            __syncthreads();
        }
    }
    float thr = srt[512 - k];

    sel[tid] = (scr[tid] > thr) ? 1 : 0;
    if (scr[tid] > thr) atomicAdd(&cgt, 1);
    __syncthreads();
    if (tid == 0) {
        int need = k - cgt;
        for (int n = 0; n < 512 && need > 0; n++) {
            if (scr[n] == thr && !sel[n]) { sel[n] = 1; need--; }
        }
    }
    __syncthreads();

    fac[tid] = sel[tid] ? tanhf(scr[tid]) : 0.f;
    g_nm[g * 512 + tid] = sel[tid];

    // next-layer active-neighbor degree (edges intra-graph; low 9 bits = local)
    {
        int v = g * 512 + tid;
        int cnt = g_cnt[v];
        const int* row = g_csr + v * SLOTS;
        int d = 0;
        for (int j = 0; j < cnt; j++) d += (int)sel[row[j] & 511];
        g_deg[v] = d;
    }
    __syncthreads();

    int c2 = tid & 63;
    int qd = tid >> 6;
    const float* hh = g_h + (size_t)g * 512 * 128;
    float* xx = g_x + (size_t)g * 512 * 128;
    float mx0 = -INFINITY, sm0 = 0.f, mx1 = -INFINITY, sm1 = 0.f;
    for (int n = qd; n < 512; n += 8) {
        float f = fac[n];
        float v0 = hh[n * 128 + 2 * c2] * f;
        float v1 = hh[n * 128 + 2 * c2 + 1] * f;
        *reinterpret_cast<float2*>(&xx[n * 128 + 2 * c2]) = make_float2(v0, v1);
        if (sel[n]) {
            mx0 = fmaxf(mx0, v0); sm0 += v0;
            mx1 = fmaxf(mx1, v1); sm1 += v1;
        }
    }
    smx[qd][2 * c2] = mx0; smx[qd][2 * c2 + 1] = mx1;
    ssm[qd][2 * c2] = sm0; ssm[qd][2 * c2 + 1] = sm1;
    __syncthreads();
    if (tid < 128) {
        float m = smx[0][tid], s = ssm[0][tid];
#pragma unroll
        for (int i = 1; i < 8; i++) { m = fmaxf(m, smx[i][tid]); s += ssm[i][tid]; }
        g_z[g * 256 + tid] += m;
        g_z[g * 256 + 128 + tid] += s / kf;
    }
}

// ---------------- MLP head + g_cnt reset for graph replay ----------------
__global__ void k_mlp(const float* __restrict__ w1, const float* __restrict__ b1,
                      const float* __restrict__ w2, const float* __restrict__ b2,
                      const float* __restrict__ w3, const float* __restrict__ b3,
                      float* __restrict__ out)
{
    int g = blockIdx.x;
    int tid = threadIdx.x;

    // reset slot allocator: 128 blocks x 128 threads x 4 ints = 65536
    {
        int i = (g * 128 + tid) * 4;
        *reinterpret_cast<int4*>(&g_cnt[i]) = make_int4(0, 0, 0, 0);
    }

    __shared__ float z[256], t1[128], t2[64];
    z[tid] = g_z[g * 256 + tid];
    z[tid + 128] = g_z[g * 256 + 128 + tid];
    __syncthreads();
    {
        float s = b1[tid];
        for (int i = 0; i < 256; i++) s += z[i] * w1[tid * 256 + i];
        t1[tid] = fmaxf(s, 0.f);
    }
    __syncthreads();
    if (tid < 64) {
        float s = b2[tid];
        for (int i = 0; i < 128; i++) s += t1[i] * w2[tid * 128 + i];
        t2[tid] = fmaxf(s, 0.f);
    }
    __syncthreads();
    if (tid == 0) {
        float s = b3[0];
        for (int i = 0; i < 64; i++) s += t2[i] * w3[i];
        out[g] = 1.f / (1.f + expf(-s));
    }
}

// ---------------- launch ----------------
extern "C" void kernel_launch(void* const* d_in, const int* in_sizes, int n_in,
                              void* d_out, int out_size) {
    const float* x  = (const float*)d_in[0];
    const int*   ei = (const int*)d_in[1];
    const float* wl[3] = { (const float*)d_in[2], (const float*)d_in[6],  (const float*)d_in[10] };
    const float* bl[3] = { (const float*)d_in[3], (const float*)d_in[7],  (const float*)d_in[11] };
    const float* wr[3] = { (const float*)d_in[4], (const float*)d_in[8],  (const float*)d_in[12] };
    const float* pw[3] = { (const float*)d_in[5], (const float*)d_in[9],  (const float*)d_in[13] };
    const float* l1w = (const float*)d_in[14];
    const float* l1b = (const float*)d_in[15];
    const float* l2w = (const float*)d_in[16];
    const float* l2b = (const float*)d_in[17];
    const float* l3w = (const float*)d_in[18];
    const float* l3b = (const float*)d_in[19];
    float* out = (float*)d_out;

    const int KS[3] = { 410, 328, 263 };

    cudaFuncSetAttribute(k_gemm, cudaFuncAttributeMaxDynamicSharedMemorySize, SMEM_GEMM);

    float* d_gx;
    cudaGetSymbolAddress((void**)&d_gx, g_x);

    k_init<<<EE / 256, 256>>>(ei, wl[0], wr[0], wl[1], wr[1], wl[2], wr[2]);

    for (int l = 0; l < 3; l++) {
        const float* xsrc = (l == 0) ? x : d_gx;
        k_aggregate<<<NN / 8, 256>>>(xsrc, l == 0 ? 1 : 0);
        k_gemm<<<NN / 128, 256, SMEM_GEMM>>>(l, bl[l], xsrc);
        k_pool<<<BB, 512>>>(pw[l], KS[l], (float)KS[l]);
    }
    k_mlp<<<BB, 128>>>(l1w, l1b, l2w, l2b, l3w, l3b, out);
}

// round 13
// speedup vs baseline: 1.0412x; 1.0412x over previous
#include <cuda_runtime.h>
#include <math.h>
#include <cstdint>

#define NN   65536
#define DD   128
#define EE   524288
#define BB   128
#define NPER 512

// ---------------- scratch (device globals; no allocs allowed) ----------------
__device__ int   g_cnt[NN];
__device__ int   g_rowptr[NN + 1];
__device__ int   g_fill[NN];
__device__ int   g_deg[NN];
__device__ int   g_csr[EE];
__device__ unsigned long long g_scanstat[256];
__device__ float g_x[NN * DD];        // pooled features (layers >= 1)
__device__ float g_score[NN];         // pool scores (GEMM epilogue atomics); kept zeroed
__device__ float g_fac[NN];           // tanh(score) or 0
__device__ uint32_t g_mH[NN * 64];
__device__ uint32_t g_mL[NN * 64];
__device__ uint32_t g_wH[6][128 * 64];
__device__ uint32_t g_wL[6][128 * 64];
__device__ float g_h[NN * DD];
__device__ unsigned char g_nm[NN];
__device__ float g_pmx[3 * 4 * BB * 128];  // readout partials: max
__device__ float g_psm[3 * 4 * BB * 128];  // readout partials: sum/k

// ---------------- helpers ----------------
__device__ __forceinline__ uint32_t pack_bf16x2(float v0, float v1) {
    uint32_t r;
    asm("cvt.rn.bf16x2.f32 %0, %1, %2;" : "=r"(r) : "f"(v1), "f"(v0));
    return r;
}
__device__ __forceinline__ float bf_lo(uint32_t u) { return __uint_as_float(u << 16); }
__device__ __forceinline__ float bf_hi(uint32_t u) { return __uint_as_float(u & 0xFFFF0000u); }

__device__ __forceinline__ void split4(float4 v, uint32_t* h, uint32_t* l) {
    h[0] = pack_bf16x2(v.x, v.y);
    l[0] = pack_bf16x2(v.x - bf_lo(h[0]), v.y - bf_hi(h[0]));
    h[1] = pack_bf16x2(v.z, v.w);
    l[1] = pack_bf16x2(v.z - bf_lo(h[1]), v.w - bf_hi(h[1]));
}

__device__ __forceinline__ void mma_bf16(float* c,
    uint32_t a0, uint32_t a1, uint32_t a2, uint32_t a3,
    uint32_t b0, uint32_t b1)
{
    asm volatile(
        "mma.sync.aligned.m16n8k16.row.col.f32.bf16.bf16.f32 "
        "{%0,%1,%2,%3},{%4,%5,%6,%7},{%8,%9},{%0,%1,%2,%3};"
        : "+f"(c[0]), "+f"(c[1]), "+f"(c[2]), "+f"(c[3])
        : "r"(a0), "r"(a1), "r"(a2), "r"(a3), "r"(b0), "r"(b1));
}

__device__ __forceinline__ void ldm_x4(uint32_t* r, uint32_t addr) {
    asm volatile("ldmatrix.sync.aligned.m8n8.x4.shared.b16 {%0,%1,%2,%3}, [%4];"
        : "=r"(r[0]), "=r"(r[1]), "=r"(r[2]), "=r"(r[3]) : "r"(addr));
}

__device__ __forceinline__ uint32_t smem_u32(const void* p) {
    uint32_t a;
    asm("{ .reg .u64 t; cvta.to.shared.u64 t, %1; cvt.u32.u64 %0, t; }" : "=r"(a) : "l"(p));
    return a;
}
__device__ __forceinline__ void cp16(uint32_t saddr, const void* gaddr) {
    asm volatile("cp.async.cg.shared.global [%0], [%1], 16;" :: "r"(saddr), "l"(gaddr) : "memory");
}
#define CP_COMMIT() asm volatile("cp.async.commit_group;" ::: "memory")
#define CP_WAIT1()  asm volatile("cp.async.wait_group 1;" ::: "memory")
#define CP_WAIT0()  asm volatile("cp.async.wait_group 0;" ::: "memory")

// ---------------- init: weight splits, mask, edge histogram ----------------
__global__ void k_init(const int* __restrict__ ei,
                       const float* w0, const float* w1, const float* w2,
                       const float* w3, const float* w4, const float* w5) {
    int i = blockIdx.x * blockDim.x + threadIdx.x;   // exactly EE threads
    if (i < NN) g_nm[i] = 1;
    if (i < 6 * 8192) {
        int m = i >> 13, j = i & 8191;
        const float* wp = (m == 0) ? w0 : (m == 1) ? w1 : (m == 2) ? w2
                         : (m == 3) ? w3 : (m == 4) ? w4 : w5;
        float2 w = reinterpret_cast<const float2*>(wp)[j];
        uint32_t wh = pack_bf16x2(w.x, w.y);
        uint32_t wl2 = pack_bf16x2(w.x - bf_lo(wh), w.y - bf_hi(wh));
        g_wH[m][j] = wh;
        g_wL[m][j] = wl2;
    }
    atomicAdd(&g_cnt[ei[EE + i]], 1);
}

// ---------------- single-kernel scan (decoupled lookback) ----------------
__global__ void k_scan() {
    __shared__ int sh[256];
    __shared__ unsigned int redv[256];
    int b = blockIdx.x, t = threadIdx.x;
    int i = b * 256 + t;
    int c = g_cnt[i];
    g_cnt[i] = 0;
    g_deg[i] = c;                      // layer-0 degree (all active)
    sh[t] = c;
    __syncthreads();
#pragma unroll
    for (int off = 1; off < 256; off <<= 1) {
        int v = (t >= off) ? sh[t - off] : 0;
        __syncthreads();
        sh[t] += v;
        __syncthreads();
    }
    if (t == 0)
        atomicExch(&g_scanstat[b], (1ULL << 32) | (unsigned long long)(unsigned)sh[255]);
    unsigned int myv = 0;
    if (t < b) {
        unsigned long long v;
        do { v = atomicAdd(&g_scanstat[t], 0ULL); } while ((v >> 32) == 0);
        myv = (unsigned int)v;
    }
    redv[t] = myv;
    __syncthreads();
#pragma unroll
    for (int off = 128; off > 0; off >>= 1) {
        if (t < off) redv[t] += redv[t + off];
        __syncthreads();
    }
    int val = (int)redv[0] + sh[t] - c;
    g_rowptr[i] = val;
    g_fill[i] = val;
    if (i == NN - 1) g_rowptr[NN] = EE;
}

__global__ void k_scatter(const int* __restrict__ src, const int* __restrict__ dst) {
    int e = blockIdx.x * blockDim.x + threadIdx.x;
    int p = atomicAdd(&g_fill[dst[e]], 1);
    g_csr[p] = src[e];
    if (e < 256) g_scanstat[e] = 0;
}

// ---------------- neighbor mean: fp32 gather ----------------
__global__ void k_aggregate(const float* __restrict__ xsrc) {
    int node = blockIdx.x * 8 + (threadIdx.x >> 5);
    int lane = threadIdx.x & 31;
    uint2* MH = reinterpret_cast<uint2*>(g_mH);
    uint2* ML = reinterpret_cast<uint2*>(g_mL);
    if (!g_nm[node]) {
        MH[node * 32 + lane] = make_uint2(0u, 0u);
        ML[node * 32 + lane] = make_uint2(0u, 0u);
        return;
    }
    int r0 = g_rowptr[node], r1 = g_rowptr[node + 1];
    const float4* X = reinterpret_cast<const float4*>(xsrc);
    float a0 = 0.f, a1 = 0.f, a2 = 0.f, a3 = 0.f;
#pragma unroll 4
    for (int e = r0; e < r1; e++) {
        int s = g_csr[e];
        float4 v = X[(size_t)s * 32 + lane];
        a0 += v.x; a1 += v.y; a2 += v.z; a3 += v.w;
    }
    int dg = g_deg[node];
    float inv = 1.f / (float)(dg > 1 ? dg : 1);
    a0 *= inv; a1 *= inv; a2 *= inv; a3 *= inv;
    uint32_t h0 = pack_bf16x2(a0, a1);
    uint32_t h1 = pack_bf16x2(a2, a3);
    uint32_t l0 = pack_bf16x2(a0 - bf_lo(h0), a1 - bf_hi(h0));
    uint32_t l1 = pack_bf16x2(a2 - bf_lo(h1), a3 - bf_hi(h1));
    MH[node * 32 + lane] = make_uint2(h0, h1);
    ML[node * 32 + lane] = make_uint2(l0, l1);
}

// ---------------- 3xBF16 GEMM + fused pool-score epilogue ----------------
#define BUF_U32   2560
#define STG_U32   10240
#define SMEM_GEMM 81920

__global__ __launch_bounds__(256, 2) void k_gemm(int layer, const float* __restrict__ bl,
                                                 const float* __restrict__ xsrc,
                                                 const float* __restrict__ pw)
{
    extern __shared__ __align__(16) uint32_t dsm[];
    __shared__ float sbias[128];
    __shared__ float spw[128];
    uint32_t sb0 = smem_u32(dsm);

    int t = threadIdx.x;
    int lane = t & 31;
    int g = lane >> 2;
    int tq = lane & 3;
    int warp = t >> 5;
    int wm = warp >> 1;
    int wn = warp & 1;
    int base = blockIdx.x * 128;
    size_t bofs = (size_t)base * 64;

    if (t < 128) { sbias[t] = bl[t]; spw[t] = pw[t]; }

    int r0c = t >> 2, q4c = (t & 3) * 4;
    int r1c = r0c + 64;

    int q = lane >> 3;
    int lr = lane & 7;
    int a_row0 = wm * 32 + (q & 1) * 8 + lr;
    int a_coladd = (q >> 1) * 4;
    int b_row0 = wn * 64 + (q >> 1) * 8 + lr;
    int b_coladd = (q & 1) * 4;

    float acc[2][8][4];
#pragma unroll
    for (int mt = 0; mt < 2; mt++)
#pragma unroll
        for (int nt = 0; nt < 8; nt++)
#pragma unroll
            for (int i = 0; i < 4; i++) acc[mt][nt][i] = 0.f;

    auto issue = [&](int c, int st) {
        const uint32_t* wH = g_wH[(layer << 1) | (c >> 2)] + (c & 3) * 16;
        const uint32_t* wLp = g_wL[(layer << 1) | (c >> 2)] + (c & 3) * 16;
        uint32_t sb = sb0 + st * (STG_U32 * 4);
        if (c < 4) {
            const uint32_t* aH = g_mH + bofs + c * 16;
            const uint32_t* aL = g_mL + bofs + c * 16;
            cp16(sb + (r0c * 20 + q4c) * 4,           aH + (size_t)r0c * 64 + q4c);
            cp16(sb + (r1c * 20 + q4c) * 4,           aH + (size_t)r1c * 64 + q4c);
            cp16(sb + (BUF_U32 + r0c * 20 + q4c) * 4, aL + (size_t)r0c * 64 + q4c);
            cp16(sb + (BUF_U32 + r1c * 20 + q4c) * 4, aL + (size_t)r1c * 64 + q4c);
        }
        cp16(sb + (2 * BUF_U32 + r0c * 20 + q4c) * 4, wH + (size_t)r0c * 64 + q4c);
        cp16(sb + (2 * BUF_U32 + r1c * 20 + q4c) * 4, wH + (size_t)r1c * 64 + q4c);
        cp16(sb + (3 * BUF_U32 + r0c * 20 + q4c) * 4, wLp + (size_t)r0c * 64 + q4c);
        cp16(sb + (3 * BUF_U32 + r1c * 20 + q4c) * 4, wLp + (size_t)r1c * 64 + q4c);
        CP_COMMIT();
    };

    float4 xv[4];
    auto ldx = [&](int c) {
        const float4* X4 = reinterpret_cast<const float4*>(xsrc) + (size_t)base * 32 + (c - 4) * 8;
#pragma unroll
        for (int j = 0; j < 4; j++) {
            int idx = t + j * 256;
            int row = idx >> 3, qq = idx & 7;
            xv[j] = X4[(size_t)row * 32 + qq];
        }
    };
    auto stx = [&](int st) {
        uint32_t* dH = dsm + st * STG_U32;
        uint32_t* dL = dH + BUF_U32;
#pragma unroll
        for (int j = 0; j < 4; j++) {
            int idx = t + j * 256;
            int row = idx >> 3, qq = idx & 7;
            uint32_t h[2], l[2];
            split4(xv[j], h, l);
            *reinterpret_cast<uint2*>(dH + row * 20 + qq * 2) = make_uint2(h[0], h[1]);
            *reinterpret_cast<uint2*>(dL + row * 20 + qq * 2) = make_uint2(l[0], l[1]);
        }
    };

    issue(0, 0);
    for (int c = 0; c < 8; c++) {
        int st = c & 1;
        if (c < 7) {
            issue(c + 1, st ^ 1);
            if (c + 1 >= 4) ldx(c + 1);
            CP_WAIT1();
        } else {
            CP_WAIT0();
        }
        __syncthreads();

        uint32_t bA_H = sb0 + st * (STG_U32 * 4);
        uint32_t bA_L = bA_H + BUF_U32 * 4;
        uint32_t bW_H = bA_H + 2 * BUF_U32 * 4;
        uint32_t bW_L = bA_H + 3 * BUF_U32 * 4;

#pragma unroll
        for (int ks = 0; ks < 2; ks++) {
            int cb = ks * 8;
            uint32_t aH[2][4], aL[2][4];
#pragma unroll
            for (int mt = 0; mt < 2; mt++) {
                uint32_t ar = ((uint32_t)((a_row0 + mt * 16) * 20 + cb + a_coladd)) * 4;
                ldm_x4(aH[mt], bA_H + ar);
                ldm_x4(aL[mt], bA_L + ar);
            }
#pragma unroll
            for (int half = 0; half < 2; half++) {
                uint32_t bh[8], blo[8];
#pragma unroll
                for (int j2 = 0; j2 < 2; j2++) {
                    uint32_t br = ((uint32_t)((b_row0 + half * 32 + j2 * 16) * 20 + cb + b_coladd)) * 4;
                    ldm_x4(&bh[j2 * 4],  bW_H + br);
                    ldm_x4(&blo[j2 * 4], bW_L + br);
                }
#pragma unroll
                for (int nt2 = 0; nt2 < 4; nt2++) {
                    int nt = half * 4 + nt2;
                    uint32_t b0h = bh[nt2 * 2], b1h = bh[nt2 * 2 + 1];
                    uint32_t b0l = blo[nt2 * 2], b1l = blo[nt2 * 2 + 1];
#pragma unroll
                    for (int mt = 0; mt < 2; mt++) {
                        mma_bf16(acc[mt][nt], aH[mt][0], aH[mt][1], aH[mt][2], aH[mt][3], b0h, b1h);
                        mma_bf16(acc[mt][nt], aH[mt][0], aH[mt][1], aH[mt][2], aH[mt][3], b0l, b1l);
                        mma_bf16(acc[mt][nt], aL[mt][0], aL[mt][1], aL[mt][2], aL[mt][3], b0h, b1h);
                    }
                }
            }
        }

        if (c < 7 && c + 1 >= 4) stx(st ^ 1);
        __syncthreads();
    }

    // epilogue: bias + relu + store h + per-row score partials
    float pr0[2] = { 0.f, 0.f };   // rows r       (mt=0,1)
    float pr8[2] = { 0.f, 0.f };   // rows r + 8
#pragma unroll
    for (int nt = 0; nt < 8; nt++) {
        int col = wn * 64 + nt * 8 + tq * 2;
        float bb0 = sbias[col];
        float bb1 = sbias[col + 1];
        float w0 = spw[col];
        float w1 = spw[col + 1];
#pragma unroll
        for (int mt = 0; mt < 2; mt++) {
            int r = base + wm * 32 + mt * 16 + g;
            float2 o;
            o.x = fmaxf(acc[mt][nt][0] + bb0, 0.f);
            o.y = fmaxf(acc[mt][nt][1] + bb1, 0.f);
            *reinterpret_cast<float2*>(&g_h[(size_t)r * 128 + col]) = o;
            pr0[mt] += o.x * w0 + o.y * w1;
            o.x = fmaxf(acc[mt][nt][2] + bb0, 0.f);
            o.y = fmaxf(acc[mt][nt][3] + bb1, 0.f);
            *reinterpret_cast<float2*>(&g_h[(size_t)(r + 8) * 128 + col]) = o;
            pr8[mt] += o.x * w0 + o.y * w1;
        }
    }
#pragma unroll
    for (int mt = 0; mt < 2; mt++) {
        pr0[mt] += __shfl_xor_sync(0xffffffffu, pr0[mt], 1);
        pr0[mt] += __shfl_xor_sync(0xffffffffu, pr0[mt], 2);
        pr8[mt] += __shfl_xor_sync(0xffffffffu, pr8[mt], 1);
        pr8[mt] += __shfl_xor_sync(0xffffffffu, pr8[mt], 2);
    }
    if (tq == 0) {
        int r = base + wm * 32 + g;
        atomicAdd(&g_score[r],      pr0[0]);
        atomicAdd(&g_score[r + 8],  pr8[0]);
        atomicAdd(&g_score[r + 16], pr0[1]);
        atomicAdd(&g_score[r + 24], pr8[1]);
    }
}

// ---------------- select: sort scores, pick top-k, fac/nm/deg ----------------
__global__ __launch_bounds__(512) void k_select(const float* __restrict__ pw, int k) {
    int g = blockIdx.x;
    int tid = threadIdx.x;

    __shared__ float scr[512];
    __shared__ float srt[512];
    __shared__ unsigned char sel[512];
    __shared__ float rsq[128];
    __shared__ float inv_norm;
    __shared__ int cgt;

    if (tid < 128) { float w = pw[tid]; rsq[tid] = w * w; }
    if (tid == 0) cgt = 0;
    __syncthreads();
    if (tid == 0) {
        float s = 0.f;
        for (int i = 0; i < 128; i++) s += rsq[i];
        inv_norm = 1.f / (sqrtf(s) + 1e-16f);
    }
    __syncthreads();

    int node = g * 512 + tid;
    float sc = g_nm[node] ? g_score[node] * inv_norm : -INFINITY;
    g_score[node] = 0.f;               // reset for next layer / replay
    scr[tid] = sc;
    srt[tid] = sc;
    __syncthreads();

    for (int kk = 2; kk <= 512; kk <<= 1) {
        for (int j = kk >> 1; j > 0; j >>= 1) {
            int ixj = tid ^ j;
            if (ixj > tid) {
                float a = srt[tid], b = srt[ixj];
                bool asc = ((tid & kk) == 0);
                if ((a > b) == asc) { srt[tid] = b; srt[ixj] = a; }
            }
            __syncthreads();
        }
    }
    float thr = srt[512 - k];

    sel[tid] = (scr[tid] > thr) ? 1 : 0;
    if (scr[tid] > thr) atomicAdd(&cgt, 1);
    __syncthreads();
    if (tid == 0) {
        int need = k - cgt;
        for (int n = 0; n < 512 && need > 0; n++) {
            if (scr[n] == thr && !sel[n]) { sel[n] = 1; need--; }
        }
    }
    __syncthreads();

    g_fac[node] = sel[tid] ? tanhf(scr[tid]) : 0.f;
    g_nm[node] = sel[tid];

    // next-layer active-neighbor degree (edges intra-graph; low 9 bits local)
    int r0 = g_rowptr[node], r1 = g_rowptr[node + 1];
    int d = 0;
    for (int e = r0; e < r1; e++) d += (int)sel[g_csr[e] & 511];
    g_deg[node] = d;
}

// ---------------- readout: x = h*fac + per-quarter column max/sum ----------
__global__ __launch_bounds__(256) void k_readout(int layer, float invk) {
    int b = blockIdx.x;
    int g = b >> 2, qq = b & 3;
    int tid = threadIdx.x;

    __shared__ float sfac[128];
    __shared__ unsigned char snm[128];
    __shared__ float pm[2][128];
    __shared__ float ps[2][128];

    int n0 = qq * 128;
    if (tid < 128) {
        int node = g * 512 + n0 + tid;
        sfac[tid] = g_fac[node];
        snm[tid] = g_nm[node];
    }
    __syncthreads();

    int c = tid & 127;
    int half = tid >> 7;
    const float* hh = g_h + (size_t)(g * 512 + n0) * 128;
    float* xx = g_x + (size_t)(g * 512 + n0) * 128;
    float mx = -INFINITY, sm = 0.f;
#pragma unroll 4
    for (int j = 0; j < 64; j++) {
        int n = half * 64 + j;
        float v = hh[n * 128 + c] * sfac[n];
        xx[n * 128 + c] = v;
        if (snm[n]) { mx = fmaxf(mx, v); sm += v; }
    }
    pm[half][c] = mx;
    ps[half][c] = sm;
    __syncthreads();
    if (tid < 128) {
        float m = fmaxf(pm[0][tid], pm[1][tid]);
        float s = ps[0][tid] + ps[1][tid];
        int idx = ((layer * 4 + qq) * BB + g) * 128 + tid;
        g_pmx[idx] = m;
        g_psm[idx] = s * invk;
    }
}

// ---------------- MLP head (combines readout partials) ----------------
__global__ void k_mlp(const float* __restrict__ w1, const float* __restrict__ b1,
                      const float* __restrict__ w2, const float* __restrict__ b2,
                      const float* __restrict__ w3, const float* __restrict__ b3,
                      float* __restrict__ out)
{
    int g = blockIdx.x;
    int tid = threadIdx.x;
    __shared__ float z[256], t1[128], t2[64];

    {
        float zm = 0.f, zs = 0.f;
#pragma unroll
        for (int l = 0; l < 3; l++) {
            float m = -INFINITY, s = 0.f;
#pragma unroll
            for (int qq = 0; qq < 4; qq++) {
                int idx = ((l * 4 + qq) * BB + g) * 128 + tid;
                m = fmaxf(m, g_pmx[idx]);
                s += g_psm[idx];
            }
            zm += m;
            zs += s;
        }
        z[tid] = zm;
        z[tid + 128] = zs;
    }
    __syncthreads();
    {
        float s = b1[tid];
        for (int i = 0; i < 256; i++) s += z[i] * w1[tid * 256 + i];
        t1[tid] = fmaxf(s, 0.f);
    }
    __syncthreads();
    if (tid < 64) {
        float s = b2[tid];
        for (int i = 0; i < 128; i++) s += t1[i] * w2[tid * 128 + i];
        t2[tid] = fmaxf(s, 0.f);
    }
    __syncthreads();
    if (tid == 0) {
        float s = b3[0];
        for (int i = 0; i < 64; i++) s += t2[i] * w3[i];
        out[g] = 1.f / (1.f + expf(-s));
    }
}

// ---------------- launch ----------------
extern "C" void kernel_launch(void* const* d_in, const int* in_sizes, int n_in,
                              void* d_out, int out_size) {
    const float* x  = (const float*)d_in[0];
    const int*   ei = (const int*)d_in[1];
    const float* wl[3] = { (const float*)d_in[2], (const float*)d_in[6],  (const float*)d_in[10] };
    const float* bl[3] = { (const float*)d_in[3], (const float*)d_in[7],  (const float*)d_in[11] };
    const float* wr[3] = { (const float*)d_in[4], (const float*)d_in[8],  (const float*)d_in[12] };
    const float* pw[3] = { (const float*)d_in[5], (const float*)d_in[9],  (const float*)d_in[13] };
    const float* l1w = (const float*)d_in[14];
    const float* l1b = (const float*)d_in[15];
    const float* l2w = (const float*)d_in[16];
    const float* l2b = (const float*)d_in[17];
    const float* l3w = (const float*)d_in[18];
    const float* l3b = (const float*)d_in[19];
    float* out = (float*)d_out;

    const int KS[3] = { 410, 328, 263 };

    cudaFuncSetAttribute(k_gemm, cudaFuncAttributeMaxDynamicSharedMemorySize, SMEM_GEMM);

    float* d_gx;
    cudaGetSymbolAddress((void**)&d_gx, g_x);

    k_init<<<EE / 256, 256>>>(ei, wl[0], wr[0], wl[1], wr[1], wl[2], wr[2]);
    k_scan<<<256, 256>>>();
    k_scatter<<<EE / 256, 256>>>(ei, ei + EE);

    for (int l = 0; l < 3; l++) {
        const float* xsrc = (l == 0) ? x : d_gx;
        k_aggregate<<<NN / 8, 256>>>(xsrc);
        k_gemm<<<NN / 128, 256, SMEM_GEMM>>>(l, bl[l], xsrc, pw[l]);
        k_select<<<BB, 512>>>(pw[l], KS[l]);
        k_readout<<<BB * 4, 256>>>(l, 1.f / (float)KS[l]);
    }
    k_mlp<<<BB, 128>>>(l1w, l1b, l2w, l2b, l3w, l3b, out);
}

// round 14
// speedup vs baseline: 1.1753x; 1.1288x over previous
#include <cuda_runtime.h>
#include <math.h>
#include <cstdint>

#define NN   65536
#define DD   128
#define EE   524288
#define BB   128
#define NPER 512

// ---------------- scratch (device globals; no allocs allowed) ----------------
__device__ int   g_cnt[NN];
__device__ int   g_rowptr[NN + 1];
__device__ int   g_fill[NN];
__device__ int   g_deg[NN];
__device__ int   g_csr[EE];
__device__ unsigned long long g_scanstat[256];
__device__ float g_x[NN * DD];        // pooled features (layers >= 1)
__device__ float g_fac[NN];           // tanh(score) or 0
__device__ uint32_t g_mH[NN * 64];
__device__ uint32_t g_mL[NN * 64];
__device__ uint32_t g_wH[6][128 * 64];
__device__ uint32_t g_wL[6][128 * 64];
__device__ float g_h[NN * DD];
__device__ unsigned char g_nm[NN];
__device__ float g_pmx[3 * 4 * BB * 128];  // readout partials: max
__device__ float g_psm[3 * 4 * BB * 128];  // readout partials: sum/k

// ---------------- helpers ----------------
__device__ __forceinline__ uint32_t pack_bf16x2(float v0, float v1) {
    uint32_t r;
    asm("cvt.rn.bf16x2.f32 %0, %1, %2;" : "=r"(r) : "f"(v1), "f"(v0));
    return r;
}
__device__ __forceinline__ float bf_lo(uint32_t u) { return __uint_as_float(u << 16); }
__device__ __forceinline__ float bf_hi(uint32_t u) { return __uint_as_float(u & 0xFFFF0000u); }

__device__ __forceinline__ void split4(float4 v, uint32_t* h, uint32_t* l) {
    h[0] = pack_bf16x2(v.x, v.y);
    l[0] = pack_bf16x2(v.x - bf_lo(h[0]), v.y - bf_hi(h[0]));
    h[1] = pack_bf16x2(v.z, v.w);
    l[1] = pack_bf16x2(v.z - bf_lo(h[1]), v.w - bf_hi(h[1]));
}

__device__ __forceinline__ void mma_bf16(float* c,
    uint32_t a0, uint32_t a1, uint32_t a2, uint32_t a3,
    uint32_t b0, uint32_t b1)
{
    asm volatile(
        "mma.sync.aligned.m16n8k16.row.col.f32.bf16.bf16.f32 "
        "{%0,%1,%2,%3},{%4,%5,%6,%7},{%8,%9},{%0,%1,%2,%3};"
        : "+f"(c[0]), "+f"(c[1]), "+f"(c[2]), "+f"(c[3])
        : "r"(a0), "r"(a1), "r"(a2), "r"(a3), "r"(b0), "r"(b1));
}

__device__ __forceinline__ void ldm_x4(uint32_t* r, uint32_t addr) {
    asm volatile("ldmatrix.sync.aligned.m8n8.x4.shared.b16 {%0,%1,%2,%3}, [%4];"
        : "=r"(r[0]), "=r"(r[1]), "=r"(r[2]), "=r"(r[3]) : "r"(addr));
}

__device__ __forceinline__ uint32_t smem_u32(const void* p) {
    uint32_t a;
    asm("{ .reg .u64 t; cvta.to.shared.u64 t, %1; cvt.u32.u64 %0, t; }" : "=r"(a) : "l"(p));
    return a;
}
__device__ __forceinline__ void cp16(uint32_t saddr, const void* gaddr) {
    asm volatile("cp.async.cg.shared.global [%0], [%1], 16;" :: "r"(saddr), "l"(gaddr) : "memory");
}
#define CP_COMMIT() asm volatile("cp.async.commit_group;" ::: "memory")
#define CP_WAIT1()  asm volatile("cp.async.wait_group 1;" ::: "memory")
#define CP_WAIT0()  asm volatile("cp.async.wait_group 0;" ::: "memory")

// ---------------- init: weight splits, mask, edge histogram ----------------
__global__ void k_init(const int* __restrict__ ei,
                       const float* w0, const float* w1, const float* w2,
                       const float* w3, const float* w4, const float* w5) {
    int i = blockIdx.x * blockDim.x + threadIdx.x;   // exactly EE threads
    if (i < NN) g_nm[i] = 1;
    if (i < 6 * 8192) {
        int m = i >> 13, j = i & 8191;
        const float* wp = (m == 0) ? w0 : (m == 1) ? w1 : (m == 2) ? w2
                         : (m == 3) ? w3 : (m == 4) ? w4 : w5;
        float2 w = reinterpret_cast<const float2*>(wp)[j];
        uint32_t wh = pack_bf16x2(w.x, w.y);
        uint32_t wl2 = pack_bf16x2(w.x - bf_lo(wh), w.y - bf_hi(wh));
        g_wH[m][j] = wh;
        g_wL[m][j] = wl2;
    }
    atomicAdd(&g_cnt[ei[EE + i]], 1);
}

// ---------------- single-kernel scan (decoupled lookback) ----------------
__global__ void k_scan() {
    __shared__ int sh[256];
    __shared__ unsigned int redv[256];
    int b = blockIdx.x, t = threadIdx.x;
    int i = b * 256 + t;
    int c = g_cnt[i];
    g_cnt[i] = 0;
    g_deg[i] = c;                      // layer-0 degree (all active)
    sh[t] = c;
    __syncthreads();
#pragma unroll
    for (int off = 1; off < 256; off <<= 1) {
        int v = (t >= off) ? sh[t - off] : 0;
        __syncthreads();
        sh[t] += v;
        __syncthreads();
    }
    if (t == 0)
        atomicExch(&g_scanstat[b], (1ULL << 32) | (unsigned long long)(unsigned)sh[255]);
    unsigned int myv = 0;
    if (t < b) {
        unsigned long long v;
        do { v = atomicAdd(&g_scanstat[t], 0ULL); } while ((v >> 32) == 0);
        myv = (unsigned int)v;
    }
    redv[t] = myv;
    __syncthreads();
#pragma unroll
    for (int off = 128; off > 0; off >>= 1) {
        if (t < off) redv[t] += redv[t + off];
        __syncthreads();
    }
    int val = (int)redv[0] + sh[t] - c;
    g_rowptr[i] = val;
    g_fill[i] = val;
    if (i == NN - 1) g_rowptr[NN] = EE;
}

__global__ void k_scatter(const int* __restrict__ src, const int* __restrict__ dst) {
    int e = blockIdx.x * blockDim.x + threadIdx.x;
    int p = atomicAdd(&g_fill[dst[e]], 1);
    g_csr[p] = src[e];
    if (e < 256) g_scanstat[e] = 0;
}

// ---------------- neighbor mean: fp32 gather ----------------
__global__ void k_aggregate(const float* __restrict__ xsrc) {
    int node = blockIdx.x * 8 + (threadIdx.x >> 5);
    int lane = threadIdx.x & 31;
    uint2* MH = reinterpret_cast<uint2*>(g_mH);
    uint2* ML = reinterpret_cast<uint2*>(g_mL);
    if (!g_nm[node]) {
        MH[node * 32 + lane] = make_uint2(0u, 0u);
        ML[node * 32 + lane] = make_uint2(0u, 0u);
        return;
    }
    int r0 = g_rowptr[node], r1 = g_rowptr[node + 1];
    const float4* X = reinterpret_cast<const float4*>(xsrc);
    float a0 = 0.f, a1 = 0.f, a2 = 0.f, a3 = 0.f;
#pragma unroll 4
    for (int e = r0; e < r1; e++) {
        int s = g_csr[e];
        float4 v = X[(size_t)s * 32 + lane];
        a0 += v.x; a1 += v.y; a2 += v.z; a3 += v.w;
    }
    int dg = g_deg[node];
    float inv = 1.f / (float)(dg > 1 ? dg : 1);
    a0 *= inv; a1 *= inv; a2 *= inv; a3 *= inv;
    uint32_t h0 = pack_bf16x2(a0, a1);
    uint32_t h1 = pack_bf16x2(a2, a3);
    uint32_t l0 = pack_bf16x2(a0 - bf_lo(h0), a1 - bf_hi(h0));
    uint32_t l1 = pack_bf16x2(a2 - bf_lo(h1), a3 - bf_hi(h1));
    MH[node * 32 + lane] = make_uint2(h0, h1);
    ML[node * 32 + lane] = make_uint2(l0, l1);
}

// ---------------- 3xBF16 GEMM (R11 version, untouched epilogue) ----------
#define BUF_U32   2560
#define STG_U32   10240
#define SMEM_GEMM 81920

__global__ __launch_bounds__(256, 2) void k_gemm(int layer, const float* __restrict__ bl,
                                                 const float* __restrict__ xsrc)
{
    extern __shared__ __align__(16) uint32_t dsm[];
    __shared__ float sbias[128];
    uint32_t sb0 = smem_u32(dsm);

    int t = threadIdx.x;
    int lane = t & 31;
    int g = lane >> 2;
    int tq = lane & 3;
    int warp = t >> 5;
    int wm = warp >> 1;
    int wn = warp & 1;
    int base = blockIdx.x * 128;
    size_t bofs = (size_t)base * 64;

    if (t < 128) sbias[t] = bl[t];

    int r0c = t >> 2, q4c = (t & 3) * 4;
    int r1c = r0c + 64;

    int q = lane >> 3;
    int lr = lane & 7;
    int a_row0 = wm * 32 + (q & 1) * 8 + lr;
    int a_coladd = (q >> 1) * 4;
    int b_row0 = wn * 64 + (q >> 1) * 8 + lr;
    int b_coladd = (q & 1) * 4;

    float acc[2][8][4];
#pragma unroll
    for (int mt = 0; mt < 2; mt++)
#pragma unroll
        for (int nt = 0; nt < 8; nt++)
#pragma unroll
            for (int i = 0; i < 4; i++) acc[mt][nt][i] = 0.f;

    auto issue = [&](int c, int st) {
        const uint32_t* wH = g_wH[(layer << 1) | (c >> 2)] + (c & 3) * 16;
        const uint32_t* wLp = g_wL[(layer << 1) | (c >> 2)] + (c & 3) * 16;
        uint32_t sb = sb0 + st * (STG_U32 * 4);
        if (c < 4) {
            const uint32_t* aH = g_mH + bofs + c * 16;
            const uint32_t* aL = g_mL + bofs + c * 16;
            cp16(sb + (r0c * 20 + q4c) * 4,           aH + (size_t)r0c * 64 + q4c);
            cp16(sb + (r1c * 20 + q4c) * 4,           aH + (size_t)r1c * 64 + q4c);
            cp16(sb + (BUF_U32 + r0c * 20 + q4c) * 4, aL + (size_t)r0c * 64 + q4c);
            cp16(sb + (BUF_U32 + r1c * 20 + q4c) * 4, aL + (size_t)r1c * 64 + q4c);
        }
        cp16(sb + (2 * BUF_U32 + r0c * 20 + q4c) * 4, wH + (size_t)r0c * 64 + q4c);
        cp16(sb + (2 * BUF_U32 + r1c * 20 + q4c) * 4, wH + (size_t)r1c * 64 + q4c);
        cp16(sb + (3 * BUF_U32 + r0c * 20 + q4c) * 4, wLp + (size_t)r0c * 64 + q4c);
        cp16(sb + (3 * BUF_U32 + r1c * 20 + q4c) * 4, wLp + (size_t)r1c * 64 + q4c);
        CP_COMMIT();
    };

    float4 xv[4];
    auto ldx = [&](int c) {
        const float4* X4 = reinterpret_cast<const float4*>(xsrc) + (size_t)base * 32 + (c - 4) * 8;
#pragma unroll
        for (int j = 0; j < 4; j++) {
            int idx = t + j * 256;
            int row = idx >> 3, qq = idx & 7;
            xv[j] = X4[(size_t)row * 32 + qq];
        }
    };
    auto stx = [&](int st) {
        uint32_t* dH = dsm + st * STG_U32;
        uint32_t* dL = dH + BUF_U32;
#pragma unroll
        for (int j = 0; j < 4; j++) {
            int idx = t + j * 256;
            int row = idx >> 3, qq = idx & 7;
            uint32_t h[2], l[2];
            split4(xv[j], h, l);
            *reinterpret_cast<uint2*>(dH + row * 20 + qq * 2) = make_uint2(h[0], h[1]);
            *reinterpret_cast<uint2*>(dL + row * 20 + qq * 2) = make_uint2(l[0], l[1]);
        }
    };

    issue(0, 0);
    for (int c = 0; c < 8; c++) {
        int st = c & 1;
        if (c < 7) {
            issue(c + 1, st ^ 1);
            if (c + 1 >= 4) ldx(c + 1);
            CP_WAIT1();
        } else {
            CP_WAIT0();
        }
        __syncthreads();

        uint32_t bA_H = sb0 + st * (STG_U32 * 4);
        uint32_t bA_L = bA_H + BUF_U32 * 4;
        uint32_t bW_H = bA_H + 2 * BUF_U32 * 4;
        uint32_t bW_L = bA_H + 3 * BUF_U32 * 4;

#pragma unroll
        for (int ks = 0; ks < 2; ks++) {
            int cb = ks * 8;
            uint32_t aH[2][4], aL[2][4];
#pragma unroll
            for (int mt = 0; mt < 2; mt++) {
                uint32_t ar = ((uint32_t)((a_row0 + mt * 16) * 20 + cb + a_coladd)) * 4;
                ldm_x4(aH[mt], bA_H + ar);
                ldm_x4(aL[mt], bA_L + ar);
            }
#pragma unroll
            for (int half = 0; half < 2; half++) {
                uint32_t bh[8], blo[8];
#pragma unroll
                for (int j2 = 0; j2 < 2; j2++) {
                    uint32_t br = ((uint32_t)((b_row0 + half * 32 + j2 * 16) * 20 + cb + b_coladd)) * 4;
                    ldm_x4(&bh[j2 * 4],  bW_H + br);
                    ldm_x4(&blo[j2 * 4], bW_L + br);
                }
#pragma unroll
                for (int nt2 = 0; nt2 < 4; nt2++) {
                    int nt = half * 4 + nt2;
                    uint32_t b0h = bh[nt2 * 2], b1h = bh[nt2 * 2 + 1];
                    uint32_t b0l = blo[nt2 * 2], b1l = blo[nt2 * 2 + 1];
#pragma unroll
                    for (int mt = 0; mt < 2; mt++) {
                        mma_bf16(acc[mt][nt], aH[mt][0], aH[mt][1], aH[mt][2], aH[mt][3], b0h, b1h);
                        mma_bf16(acc[mt][nt], aH[mt][0], aH[mt][1], aH[mt][2], aH[mt][3], b0l, b1l);
                        mma_bf16(acc[mt][nt], aL[mt][0], aL[mt][1], aL[mt][2], aL[mt][3], b0h, b1h);
                    }
                }
            }
        }

        if (c < 7 && c + 1 >= 4) stx(st ^ 1);
        __syncthreads();
    }

#pragma unroll
    for (int nt = 0; nt < 8; nt++) {
        int col = wn * 64 + nt * 8 + tq * 2;
        float bb0 = sbias[col];
        float bb1 = sbias[col + 1];
#pragma unroll
        for (int mt = 0; mt < 2; mt++) {
            int r = base + wm * 32 + mt * 16 + g;
            float2 o;
            o.x = fmaxf(acc[mt][nt][0] + bb0, 0.f);
            o.y = fmaxf(acc[mt][nt][1] + bb1, 0.f);
            *reinterpret_cast<float2*>(&g_h[(size_t)r * 128 + col]) = o;
            o.x = fmaxf(acc[mt][nt][2] + bb0, 0.f);
            o.y = fmaxf(acc[mt][nt][3] + bb1, 0.f);
            *reinterpret_cast<float2*>(&g_h[(size_t)(r + 8) * 128 + col]) = o;
        }
    }
}

// ---------------- pool: score + radix-count top-k select + fac/nm/deg -------
// No sort: exact k-th-largest via 32 rounds of __syncthreads_count over
// monotonic uint keys; ties broken lowest-index-first via warp ballots.
__global__ __launch_bounds__(512) void k_pool(const float* __restrict__ pw, int k) {
    int g = blockIdx.x;
    int tid = threadIdx.x;
    int wid = tid >> 5, lane = tid & 31;

    __shared__ float w[128];
    __shared__ float scr[512];
    __shared__ unsigned char sel[512];
    __shared__ int wcnt[16];
    __shared__ float inv_norm_s;

    if (tid < 128) w[tid] = pw[tid];
    __syncthreads();
    if (tid == 0) {
        float s = 0.f;
        for (int i = 0; i < 128; i++) s += w[i] * w[i];
        inv_norm_s = 1.f / (sqrtf(s) + 1e-16f);
    }
    __syncthreads();
    float inv_norm = inv_norm_s;

    // scores: warp per node
    for (int n = wid; n < 512; n += 16) {
        int node = g * 512 + n;
        float4 p = reinterpret_cast<const float4*>(g_h + (size_t)node * 128)[lane];
        float4 ww = reinterpret_cast<const float4*>(w)[lane];
        float d = p.x * ww.x + p.y * ww.y + p.z * ww.z + p.w * ww.w;
#pragma unroll
        for (int off = 16; off > 0; off >>= 1)
            d += __shfl_xor_sync(0xffffffffu, d, off);
        if (lane == 0)
            scr[n] = g_nm[node] ? d * inv_norm : -INFINITY;
    }
    __syncthreads();

    float sc = scr[tid];
    uint32_t u = __float_as_uint(sc);
    uint32_t key = (u & 0x80000000u) ? ~u : (u | 0x80000000u);  // monotonic

    // radix select: find exact key value of the k-th largest
    uint32_t prefix = 0;
    int base = 0;   // count of keys strictly greater on decided bits
#pragma unroll
    for (int i = 31; i >= 0; i--) {
        uint32_t bit = 1u << i;
        uint32_t himask = ~((bit << 1) - 1u);   // i=31: (bit<<1)=0 -> himask=0
        int pred = ((key & himask) == prefix) && (key & bit);
        int c = __syncthreads_count(pred);
        if (base + c >= k) prefix |= bit;
        else base += c;
    }
    // base = count(key > prefix); need = ties to take, lowest index first
    int need = k - base;
    bool tie = (key == prefix);
    unsigned bal = __ballot_sync(0xffffffffu, tie);
    if (lane == 0) wcnt[wid] = __popc(bal);
    __syncthreads();
    int wbase = 0;
#pragma unroll
    for (int wq = 0; wq < 16; wq++) wbase += (wq < wid) ? wcnt[wq] : 0;
    int rank = wbase + __popc(bal & ((1u << lane) - 1u));
    bool s = (key > prefix) || (tie && rank < need);

    sel[tid] = s ? 1 : 0;
    int node = g * 512 + tid;
    g_fac[node] = s ? tanhf(sc) : 0.f;
    g_nm[node] = s ? 1 : 0;
    __syncthreads();

    // next-layer active-neighbor degree (edges intra-graph; low 9 bits local)
    int r0 = g_rowptr[node], r1 = g_rowptr[node + 1];
    int dsum = 0;
    for (int e = r0; e < r1; e++) dsum += (int)sel[g_csr[e] & 511];
    g_deg[node] = dsum;
}

// ---------------- readout: x = h*fac + per-quarter column max/sum ----------
__global__ __launch_bounds__(256) void k_readout(int layer, float invk) {
    int b = blockIdx.x;
    int g = b >> 2, qq = b & 3;
    int tid = threadIdx.x;

    __shared__ float sfac[128];
    __shared__ unsigned char snm[128];
    __shared__ float pm[2][128];
    __shared__ float ps[2][128];

    int n0 = qq * 128;
    if (tid < 128) {
        int node = g * 512 + n0 + tid;
        sfac[tid] = g_fac[node];
        snm[tid] = g_nm[node];
    }
    __syncthreads();

    int c = tid & 127;
    int half = tid >> 7;
    const float* hh = g_h + (size_t)(g * 512 + n0) * 128;
    float* xx = g_x + (size_t)(g * 512 + n0) * 128;
    float mx = -INFINITY, sm = 0.f;
#pragma unroll 4
    for (int j = 0; j < 64; j++) {
        int n = half * 64 + j;
        float v = hh[n * 128 + c] * sfac[n];
        xx[n * 128 + c] = v;
        if (snm[n]) { mx = fmaxf(mx, v); sm += v; }
    }
    pm[half][c] = mx;
    ps[half][c] = sm;
    __syncthreads();
    if (tid < 128) {
        float m = fmaxf(pm[0][tid], pm[1][tid]);
        float s = ps[0][tid] + ps[1][tid];
        int idx = ((layer * 4 + qq) * BB + g) * 128 + tid;
        g_pmx[idx] = m;
        g_psm[idx] = s * invk;
    }
}

// ---------------- MLP head (combines readout partials) ----------------
__global__ void k_mlp(const float* __restrict__ w1, const float* __restrict__ b1,
                      const float* __restrict__ w2, const float* __restrict__ b2,
                      const float* __restrict__ w3, const float* __restrict__ b3,
                      float* __restrict__ out)
{
    int g = blockIdx.x;
    int tid = threadIdx.x;
    __shared__ float z[256], t1[128], t2[64];

    {
        float zm = 0.f, zs = 0.f;
#pragma unroll
        for (int l = 0; l < 3; l++) {
            float m = -INFINITY, s = 0.f;
#pragma unroll
            for (int qq = 0; qq < 4; qq++) {
                int idx = ((l * 4 + qq) * BB + g) * 128 + tid;
                m = fmaxf(m, g_pmx[idx]);
                s += g_psm[idx];
            }
            zm += m;
            zs += s;
        }
        z[tid] = zm;
        z[tid + 128] = zs;
    }
    __syncthreads();
    {
        float s = b1[tid];
        for (int i = 0; i < 256; i++) s += z[i] * w1[tid * 256 + i];
        t1[tid] = fmaxf(s, 0.f);
    }
    __syncthreads();
    if (tid < 64) {
        float s = b2[tid];
        for (int i = 0; i < 128; i++) s += t1[i] * w2[tid * 128 + i];
        t2[tid] = fmaxf(s, 0.f);
    }
    __syncthreads();
    if (tid == 0) {
        float s = b3[0];
        for (int i = 0; i < 64; i++) s += t2[i] * w3[i];
        out[g] = 1.f / (1.f + expf(-s));
    }
}

// ---------------- launch ----------------
extern "C" void kernel_launch(void* const* d_in, const int* in_sizes, int n_in,
                              void* d_out, int out_size) {
    const float* x  = (const float*)d_in[0];
    const int*   ei = (const int*)d_in[1];
    const float* wl[3] = { (const float*)d_in[2], (const float*)d_in[6],  (const float*)d_in[10] };
    const float* bl[3] = { (const float*)d_in[3], (const float*)d_in[7],  (const float*)d_in[11] };
    const float* wr[3] = { (const float*)d_in[4], (const float*)d_in[8],  (const float*)d_in[12] };
    const float* pw[3] = { (const float*)d_in[5], (const float*)d_in[9],  (const float*)d_in[13] };
    const float* l1w = (const float*)d_in[14];
    const float* l1b = (const float*)d_in[15];
    const float* l2w = (const float*)d_in[16];
    const float* l2b = (const float*)d_in[17];
    const float* l3w = (const float*)d_in[18];
    const float* l3b = (const float*)d_in[19];
    float* out = (float*)d_out;

    const int KS[3] = { 410, 328, 263 };

    cudaFuncSetAttribute(k_gemm, cudaFuncAttributeMaxDynamicSharedMemorySize, SMEM_GEMM);

    float* d_gx;
    cudaGetSymbolAddress((void**)&d_gx, g_x);

    k_init<<<EE / 256, 256>>>(ei, wl[0], wr[0], wl[1], wr[1], wl[2], wr[2]);
    k_scan<<<256, 256>>>();
    k_scatter<<<EE / 256, 256>>>(ei, ei + EE);

    for (int l = 0; l < 3; l++) {
        const float* xsrc = (l == 0) ? x : d_gx;
        k_aggregate<<<NN / 8, 256>>>(xsrc);
        k_gemm<<<NN / 128, 256, SMEM_GEMM>>>(l, bl[l], xsrc);
        k_pool<<<BB, 512>>>(pw[l], KS[l]);
        k_readout<<<BB * 4, 256>>>(l, 1.f / (float)KS[l]);
    }
    k_mlp<<<BB, 128>>>(l1w, l1b, l2w, l2b, l3w, l3b, out);
}

// round 15
// speedup vs baseline: 1.4140x; 1.2031x over previous
#include <cuda_runtime.h>
#include <math.h>
#include <cstdint>

#define NN   65536
#define DD   128
#define EE   524288
#define BB   128
#define NPER 512

// ---------------- scratch (device globals; no allocs allowed) ----------------
__device__ int   g_cnt[NN];
__device__ int   g_rowptr[NN + 1];
__device__ int   g_fill[NN];
__device__ int   g_deg[NN];
__device__ int   g_csr[EE];
__device__ unsigned long long g_scanstat[256];
__device__ float g_score[NN];         // pool scores (GEMM epilogue atomics); self-resetting
__device__ float g_fac[NN];           // tanh(score) or 0 (1.0 at layer 0)
__device__ uint32_t g_mH[NN * 64];
__device__ uint32_t g_mL[NN * 64];
__device__ uint32_t g_wH[6][128 * 64];
__device__ uint32_t g_wL[6][128 * 64];
__device__ float g_h[NN * DD];        // layer output; x is h*fac applied inline
__device__ unsigned char g_nm[NN];
__device__ float g_pmx[3 * 4 * BB * 128];  // readout partials: max
__device__ float g_psm[3 * 4 * BB * 128];  // readout partials: sum/k

// ---------------- helpers ----------------
__device__ __forceinline__ uint32_t pack_bf16x2(float v0, float v1) {
    uint32_t r;
    asm("cvt.rn.bf16x2.f32 %0, %1, %2;" : "=r"(r) : "f"(v1), "f"(v0));
    return r;
}
__device__ __forceinline__ float bf_lo(uint32_t u) { return __uint_as_float(u << 16); }
__device__ __forceinline__ float bf_hi(uint32_t u) { return __uint_as_float(u & 0xFFFF0000u); }

__device__ __forceinline__ void split4(float4 v, uint32_t* h, uint32_t* l) {
    h[0] = pack_bf16x2(v.x, v.y);
    l[0] = pack_bf16x2(v.x - bf_lo(h[0]), v.y - bf_hi(h[0]));
    h[1] = pack_bf16x2(v.z, v.w);
    l[1] = pack_bf16x2(v.z - bf_lo(h[1]), v.w - bf_hi(h[1]));
}

__device__ __forceinline__ void mma_bf16(float* c,
    uint32_t a0, uint32_t a1, uint32_t a2, uint32_t a3,
    uint32_t b0, uint32_t b1)
{
    asm volatile(
        "mma.sync.aligned.m16n8k16.row.col.f32.bf16.bf16.f32 "
        "{%0,%1,%2,%3},{%4,%5,%6,%7},{%8,%9},{%0,%1,%2,%3};"
        : "+f"(c[0]), "+f"(c[1]), "+f"(c[2]), "+f"(c[3])
        : "r"(a0), "r"(a1), "r"(a2), "r"(a3), "r"(b0), "r"(b1));
}

__device__ __forceinline__ void ldm_x4(uint32_t* r, uint32_t addr) {
    asm volatile("ldmatrix.sync.aligned.m8n8.x4.shared.b16 {%0,%1,%2,%3}, [%4];"
        : "=r"(r[0]), "=r"(r[1]), "=r"(r[2]), "=r"(r[3]) : "r"(addr));
}

__device__ __forceinline__ uint32_t smem_u32(const void* p) {
    uint32_t a;
    asm("{ .reg .u64 t; cvta.to.shared.u64 t, %1; cvt.u32.u64 %0, t; }" : "=r"(a) : "l"(p));
    return a;
}
__device__ __forceinline__ void cp16(uint32_t saddr, const void* gaddr) {
    asm volatile("cp.async.cg.shared.global [%0], [%1], 16;" :: "r"(saddr), "l"(gaddr) : "memory");
}
#define CP_COMMIT() asm volatile("cp.async.commit_group;" ::: "memory")
#define CP_WAIT1()  asm volatile("cp.async.wait_group 1;" ::: "memory")
#define CP_WAIT0()  asm volatile("cp.async.wait_group 0;" ::: "memory")

// ---------------- init: weight splits, mask, fac=1, edge histogram ----------
__global__ void k_init(const int* __restrict__ ei,
                       const float* w0, const float* w1, const float* w2,
                       const float* w3, const float* w4, const float* w5) {
    int i = blockIdx.x * blockDim.x + threadIdx.x;   // exactly EE threads
    if (i < NN) { g_nm[i] = 1; g_fac[i] = 1.0f; }
    if (i < 6 * 8192) {
        int m = i >> 13, j = i & 8191;
        const float* wp = (m == 0) ? w0 : (m == 1) ? w1 : (m == 2) ? w2
                         : (m == 3) ? w3 : (m == 4) ? w4 : w5;
        float2 w = reinterpret_cast<const float2*>(wp)[j];
        uint32_t wh = pack_bf16x2(w.x, w.y);
        uint32_t wl2 = pack_bf16x2(w.x - bf_lo(wh), w.y - bf_hi(wh));
        g_wH[m][j] = wh;
        g_wL[m][j] = wl2;
    }
    atomicAdd(&g_cnt[ei[EE + i]], 1);
}

// ---------------- single-kernel scan (decoupled lookback) ----------------
__global__ void k_scan() {
    __shared__ int sh[256];
    __shared__ unsigned int redv[256];
    int b = blockIdx.x, t = threadIdx.x;
    int i = b * 256 + t;
    int c = g_cnt[i];
    g_cnt[i] = 0;
    g_deg[i] = c;                      // layer-0 degree (all active)
    sh[t] = c;
    __syncthreads();
#pragma unroll
    for (int off = 1; off < 256; off <<= 1) {
        int v = (t >= off) ? sh[t - off] : 0;
        __syncthreads();
        sh[t] += v;
        __syncthreads();
    }
    if (t == 0)
        atomicExch(&g_scanstat[b], (1ULL << 32) | (unsigned long long)(unsigned)sh[255]);
    unsigned int myv = 0;
    if (t < b) {
        unsigned long long v;
        do { v = atomicAdd(&g_scanstat[t], 0ULL); } while ((v >> 32) == 0);
        myv = (unsigned int)v;
    }
    redv[t] = myv;
    __syncthreads();
#pragma unroll
    for (int off = 128; off > 0; off >>= 1) {
        if (t < off) redv[t] += redv[t + off];
        __syncthreads();
    }
    int val = (int)redv[0] + sh[t] - c;
    g_rowptr[i] = val;
    g_fill[i] = val;
    if (i == NN - 1) g_rowptr[NN] = EE;
}

__global__ void k_scatter(const int* __restrict__ src, const int* __restrict__ dst) {
    int e = blockIdx.x * blockDim.x + threadIdx.x;
    int p = atomicAdd(&g_fill[dst[e]], 1);
    g_csr[p] = src[e];
    if (e < 256) g_scanstat[e] = 0;
}

// ---------------- neighbor mean: gather h * fac (x applied inline) ----------
__global__ void k_aggregate(const float* __restrict__ hsrc) {
    int node = blockIdx.x * 8 + (threadIdx.x >> 5);
    int lane = threadIdx.x & 31;
    uint2* MH = reinterpret_cast<uint2*>(g_mH);
    uint2* ML = reinterpret_cast<uint2*>(g_mL);
    if (!g_nm[node]) {
        MH[node * 32 + lane] = make_uint2(0u, 0u);
        ML[node * 32 + lane] = make_uint2(0u, 0u);
        return;
    }
    int r0 = g_rowptr[node], r1 = g_rowptr[node + 1];
    const float4* X = reinterpret_cast<const float4*>(hsrc);
    float a0 = 0.f, a1 = 0.f, a2 = 0.f, a3 = 0.f;
#pragma unroll 4
    for (int e = r0; e < r1; e++) {
        int s = g_csr[e];
        float f = g_fac[s];                  // x = h * fac, applied inline
        float4 v = X[(size_t)s * 32 + lane];
        a0 += v.x * f; a1 += v.y * f; a2 += v.z * f; a3 += v.w * f;
    }
    int dg = g_deg[node];
    float inv = 1.f / (float)(dg > 1 ? dg : 1);
    a0 *= inv; a1 *= inv; a2 *= inv; a3 *= inv;
    uint32_t h0 = pack_bf16x2(a0, a1);
    uint32_t h1 = pack_bf16x2(a2, a3);
    uint32_t l0 = pack_bf16x2(a0 - bf_lo(h0), a1 - bf_hi(h0));
    uint32_t l1 = pack_bf16x2(a2 - bf_lo(h1), a3 - bf_hi(h1));
    MH[node * 32 + lane] = make_uint2(h0, h1);
    ML[node * 32 + lane] = make_uint2(l0, l1);
}

// ---------------- 3xBF16 GEMM + fac-inline A + fused score epilogue --------
#define BUF_U32   2560
#define STG_U32   10240
#define SMEM_GEMM 81920

__global__ __launch_bounds__(256, 2) void k_gemm(int layer, const float* __restrict__ bl,
                                                 const float* __restrict__ hsrc,
                                                 const float* __restrict__ pw)
{
    extern __shared__ __align__(16) uint32_t dsm[];
    __shared__ float sbias[128];
    __shared__ float spw[128];
    __shared__ float sfac[128];
    uint32_t sb0 = smem_u32(dsm);

    int t = threadIdx.x;
    int lane = t & 31;
    int g = lane >> 2;
    int tq = lane & 3;
    int warp = t >> 5;
    int wm = warp >> 1;
    int wn = warp & 1;
    int base = blockIdx.x * 128;
    size_t bofs = (size_t)base * 64;

    if (t < 128) { sbias[t] = bl[t]; spw[t] = pw[t]; sfac[t] = g_fac[base + t]; }

    int r0c = t >> 2, q4c = (t & 3) * 4;
    int r1c = r0c + 64;

    int q = lane >> 3;
    int lr = lane & 7;
    int a_row0 = wm * 32 + (q & 1) * 8 + lr;
    int a_coladd = (q >> 1) * 4;
    int b_row0 = wn * 64 + (q >> 1) * 8 + lr;
    int b_coladd = (q & 1) * 4;

    float acc[2][8][4];
#pragma unroll
    for (int mt = 0; mt < 2; mt++)
#pragma unroll
        for (int nt = 0; nt < 8; nt++)
#pragma unroll
            for (int i = 0; i < 4; i++) acc[mt][nt][i] = 0.f;

    auto issue = [&](int c, int st) {
        const uint32_t* wH = g_wH[(layer << 1) | (c >> 2)] + (c & 3) * 16;
        const uint32_t* wLp = g_wL[(layer << 1) | (c >> 2)] + (c & 3) * 16;
        uint32_t sb = sb0 + st * (STG_U32 * 4);
        if (c < 4) {
            const uint32_t* aH = g_mH + bofs + c * 16;
            const uint32_t* aL = g_mL + bofs + c * 16;
            cp16(sb + (r0c * 20 + q4c) * 4,           aH + (size_t)r0c * 64 + q4c);
            cp16(sb + (r1c * 20 + q4c) * 4,           aH + (size_t)r1c * 64 + q4c);
            cp16(sb + (BUF_U32 + r0c * 20 + q4c) * 4, aL + (size_t)r0c * 64 + q4c);
            cp16(sb + (BUF_U32 + r1c * 20 + q4c) * 4, aL + (size_t)r1c * 64 + q4c);
        }
        cp16(sb + (2 * BUF_U32 + r0c * 20 + q4c) * 4, wH + (size_t)r0c * 64 + q4c);
        cp16(sb + (2 * BUF_U32 + r1c * 20 + q4c) * 4, wH + (size_t)r1c * 64 + q4c);
        cp16(sb + (3 * BUF_U32 + r0c * 20 + q4c) * 4, wLp + (size_t)r0c * 64 + q4c);
        cp16(sb + (3 * BUF_U32 + r1c * 20 + q4c) * 4, wLp + (size_t)r1c * 64 + q4c);
        CP_COMMIT();
    };

    float4 xv[4];
    auto ldx = [&](int c) {
        const float4* X4 = reinterpret_cast<const float4*>(hsrc) + (size_t)base * 32 + (c - 4) * 8;
#pragma unroll
        for (int j = 0; j < 4; j++) {
            int idx = t + j * 256;
            int row = idx >> 3, qq = idx & 7;
            xv[j] = X4[(size_t)row * 32 + qq];
        }
    };
    auto stx = [&](int st) {
        uint32_t* dH = dsm + st * STG_U32;
        uint32_t* dL = dH + BUF_U32;
#pragma unroll
        for (int j = 0; j < 4; j++) {
            int idx = t + j * 256;
            int row = idx >> 3, qq = idx & 7;
            float f = sfac[row];              // x = h * fac, applied inline
            float4 v = xv[j];
            v.x *= f; v.y *= f; v.z *= f; v.w *= f;
            uint32_t h[2], l[2];
            split4(v, h, l);
            *reinterpret_cast<uint2*>(dH + row * 20 + qq * 2) = make_uint2(h[0], h[1]);
            *reinterpret_cast<uint2*>(dL + row * 20 + qq * 2) = make_uint2(l[0], l[1]);
        }
    };

    issue(0, 0);
    for (int c = 0; c < 8; c++) {
        int st = c & 1;
        if (c < 7) {
            issue(c + 1, st ^ 1);
            if (c + 1 >= 4) ldx(c + 1);
            CP_WAIT1();
        } else {
            CP_WAIT0();
        }
        __syncthreads();

        uint32_t bA_H = sb0 + st * (STG_U32 * 4);
        uint32_t bA_L = bA_H + BUF_U32 * 4;
        uint32_t bW_H = bA_H + 2 * BUF_U32 * 4;
        uint32_t bW_L = bA_H + 3 * BUF_U32 * 4;

#pragma unroll
        for (int ks = 0; ks < 2; ks++) {
            int cb = ks * 8;
            uint32_t aH[2][4], aL[2][4];
#pragma unroll
            for (int mt = 0; mt < 2; mt++) {
                uint32_t ar = ((uint32_t)((a_row0 + mt * 16) * 20 + cb + a_coladd)) * 4;
                ldm_x4(aH[mt], bA_H + ar);
                ldm_x4(aL[mt], bA_L + ar);
            }
#pragma unroll
            for (int half = 0; half < 2; half++) {
                uint32_t bh[8], blo[8];
#pragma unroll
                for (int j2 = 0; j2 < 2; j2++) {
                    uint32_t br = ((uint32_t)((b_row0 + half * 32 + j2 * 16) * 20 + cb + b_coladd)) * 4;
                    ldm_x4(&bh[j2 * 4],  bW_H + br);
                    ldm_x4(&blo[j2 * 4], bW_L + br);
                }
#pragma unroll
                for (int nt2 = 0; nt2 < 4; nt2++) {
                    int nt = half * 4 + nt2;
                    uint32_t b0h = bh[nt2 * 2], b1h = bh[nt2 * 2 + 1];
                    uint32_t b0l = blo[nt2 * 2], b1l = blo[nt2 * 2 + 1];
#pragma unroll
                    for (int mt = 0; mt < 2; mt++) {
                        mma_bf16(acc[mt][nt], aH[mt][0], aH[mt][1], aH[mt][2], aH[mt][3], b0h, b1h);
                        mma_bf16(acc[mt][nt], aH[mt][0], aH[mt][1], aH[mt][2], aH[mt][3], b0l, b1l);
                        mma_bf16(acc[mt][nt], aL[mt][0], aL[mt][1], aL[mt][2], aL[mt][3], b0h, b1h);
                    }
                }
            }
        }

        if (c < 7 && c + 1 >= 4) stx(st ^ 1);
        __syncthreads();
    }

    // epilogue: bias + relu + store h + per-row score partials
    float pr0[2] = { 0.f, 0.f };
    float pr8[2] = { 0.f, 0.f };
#pragma unroll
    for (int nt = 0; nt < 8; nt++) {
        int col = wn * 64 + nt * 8 + tq * 2;
        float bb0 = sbias[col];
        float bb1 = sbias[col + 1];
        float w0 = spw[col];
        float w1 = spw[col + 1];
#pragma unroll
        for (int mt = 0; mt < 2; mt++) {
            int r = base + wm * 32 + mt * 16 + g;
            float2 o;
            o.x = fmaxf(acc[mt][nt][0] + bb0, 0.f);
            o.y = fmaxf(acc[mt][nt][1] + bb1, 0.f);
            *reinterpret_cast<float2*>(&g_h[(size_t)r * 128 + col]) = o;
            pr0[mt] += o.x * w0 + o.y * w1;
            o.x = fmaxf(acc[mt][nt][2] + bb0, 0.f);
            o.y = fmaxf(acc[mt][nt][3] + bb1, 0.f);
            *reinterpret_cast<float2*>(&g_h[(size_t)(r + 8) * 128 + col]) = o;
            pr8[mt] += o.x * w0 + o.y * w1;
        }
    }
#pragma unroll
    for (int mt = 0; mt < 2; mt++) {
        pr0[mt] += __shfl_xor_sync(0xffffffffu, pr0[mt], 1);
        pr0[mt] += __shfl_xor_sync(0xffffffffu, pr0[mt], 2);
        pr8[mt] += __shfl_xor_sync(0xffffffffu, pr8[mt], 1);
        pr8[mt] += __shfl_xor_sync(0xffffffffu, pr8[mt], 2);
    }
    if (tq == 0) {
        int r = base + wm * 32 + g;
        atomicAdd(&g_score[r],      pr0[0]);
        atomicAdd(&g_score[r + 8],  pr8[0]);
        atomicAdd(&g_score[r + 16], pr0[1]);
        atomicAdd(&g_score[r + 24], pr8[1]);
    }
}

// ---------------- pool: radix-count top-k select on g_score ----------------
__global__ __launch_bounds__(512) void k_pool(const float* __restrict__ pw, int k) {
    int g = blockIdx.x;
    int tid = threadIdx.x;
    int wid = tid >> 5, lane = tid & 31;

    __shared__ unsigned char sel[512];
    __shared__ int wcnt[16];
    __shared__ float rsq[128];
    __shared__ float inv_norm_s;

    if (tid < 128) { float w = pw[tid]; rsq[tid] = w * w; }
    __syncthreads();
    if (tid == 0) {
        float s = 0.f;
        for (int i = 0; i < 128; i++) s += rsq[i];
        inv_norm_s = 1.f / (sqrtf(s) + 1e-16f);
    }
    __syncthreads();

    int node = g * 512 + tid;
    float sc = g_nm[node] ? g_score[node] * inv_norm_s : -INFINITY;
    g_score[node] = 0.f;               // reset for next layer / replay

    uint32_t u = __float_as_uint(sc);
    uint32_t key = (u & 0x80000000u) ? ~u : (u | 0x80000000u);  // monotonic

    uint32_t prefix = 0;
    int base = 0;
#pragma unroll
    for (int i = 31; i >= 0; i--) {
        uint32_t bit = 1u << i;
        uint32_t himask = ~((bit << 1) - 1u);
        int pred = ((key & himask) == prefix) && (key & bit);
        int c = __syncthreads_count(pred);
        if (base + c >= k) prefix |= bit;
        else base += c;
    }
    int need = k - base;
    bool tie = (key == prefix);
    unsigned bal = __ballot_sync(0xffffffffu, tie);
    if (lane == 0) wcnt[wid] = __popc(bal);
    __syncthreads();
    int wbase = 0;
#pragma unroll
    for (int wq = 0; wq < 16; wq++) wbase += (wq < wid) ? wcnt[wq] : 0;
    int rank = wbase + __popc(bal & ((1u << lane) - 1u));
    bool s = (key > prefix) || (tie && rank < need);

    sel[tid] = s ? 1 : 0;
    g_fac[node] = s ? tanhf(sc) : 0.f;
    g_nm[node] = s ? 1 : 0;
    __syncthreads();

    int r0 = g_rowptr[node], r1 = g_rowptr[node + 1];
    int dsum = 0;
    for (int e = r0; e < r1; e++) dsum += (int)sel[g_csr[e] & 511];
    g_deg[node] = dsum;
}

// ---------------- readout: column max/sum of h*fac (read-only) --------------
__global__ __launch_bounds__(256) void k_readout(int layer, float invk) {
    int b = blockIdx.x;
    int g = b >> 2, qq = b & 3;
    int tid = threadIdx.x;

    __shared__ float sfac[128];
    __shared__ unsigned char snm[128];
    __shared__ float pm[2][128];
    __shared__ float ps[2][128];

    int n0 = qq * 128;
    if (tid < 128) {
        int node = g * 512 + n0 + tid;
        sfac[tid] = g_fac[node];
        snm[tid] = g_nm[node];
    }
    __syncthreads();

    int c = tid & 127;
    int half = tid >> 7;
    const float* hh = g_h + (size_t)(g * 512 + n0) * 128;
    float mx = -INFINITY, sm = 0.f;
#pragma unroll 4
    for (int j = 0; j < 64; j++) {
        int n = half * 64 + j;
        float v = hh[n * 128 + c] * sfac[n];
        if (snm[n]) { mx = fmaxf(mx, v); sm += v; }
    }
    pm[half][c] = mx;
    ps[half][c] = sm;
    __syncthreads();
    if (tid < 128) {
        float m = fmaxf(pm[0][tid], pm[1][tid]);
        float s = ps[0][tid] + ps[1][tid];
        int idx = ((layer * 4 + qq) * BB + g) * 128 + tid;
        g_pmx[idx] = m;
        g_psm[idx] = s * invk;
    }
}

// ---------------- MLP head (combines readout partials) ----------------
__global__ void k_mlp(const float* __restrict__ w1, const float* __restrict__ b1,
                      const float* __restrict__ w2, const float* __restrict__ b2,
                      const float* __restrict__ w3, const float* __restrict__ b3,
                      float* __restrict__ out)
{
    int g = blockIdx.x;
    int tid = threadIdx.x;
    __shared__ float z[256], t1[128], t2[64];

    {
        float zm = 0.f, zs = 0.f;
#pragma unroll
        for (int l = 0; l < 3; l++) {
            float m = -INFINITY, s = 0.f;
#pragma unroll
            for (int qq = 0; qq < 4; qq++) {
                int idx = ((l * 4 + qq) * BB + g) * 128 + tid;
                m = fmaxf(m, g_pmx[idx]);
                s += g_psm[idx];
            }
            zm += m;
            zs += s;
        }
        z[tid] = zm;
        z[tid + 128] = zs;
    }
    __syncthreads();
    {
        float s = b1[tid];
        for (int i = 0; i < 256; i++) s += z[i] * w1[tid * 256 + i];
        t1[tid] = fmaxf(s, 0.f);
    }
    __syncthreads();
    if (tid < 64) {
        float s = b2[tid];
        for (int i = 0; i < 128; i++) s += t1[i] * w2[tid * 128 + i];
        t2[tid] = fmaxf(s, 0.f);
    }
    __syncthreads();
    if (tid == 0) {
        float s = b3[0];
        for (int i = 0; i < 64; i++) s += t2[i] * w3[i];
        out[g] = 1.f / (1.f + expf(-s));
    }
}

// ---------------- launch ----------------
extern "C" void kernel_launch(void* const* d_in, const int* in_sizes, int n_in,
                              void* d_out, int out_size) {
    const float* x  = (const float*)d_in[0];
    const int*   ei = (const int*)d_in[1];
    const float* wl[3] = { (const float*)d_in[2], (const float*)d_in[6],  (const float*)d_in[10] };
    const float* bl[3] = { (const float*)d_in[3], (const float*)d_in[7],  (const float*)d_in[11] };
    const float* wr[3] = { (const float*)d_in[4], (const float*)d_in[8],  (const float*)d_in[12] };
    const float* pw[3] = { (const float*)d_in[5], (const float*)d_in[9],  (const float*)d_in[13] };
    const float* l1w = (const float*)d_in[14];
    const float* l1b = (const float*)d_in[15];
    const float* l2w = (const float*)d_in[16];
    const float* l2b = (const float*)d_in[17];
    const float* l3w = (const float*)d_in[18];
    const float* l3b = (const float*)d_in[19];
    float* out = (float*)d_out;

    const int KS[3] = { 410, 328, 263 };

    cudaFuncSetAttribute(k_gemm, cudaFuncAttributeMaxDynamicSharedMemorySize, SMEM_GEMM);

    float* d_gh;
    cudaGetSymbolAddress((void**)&d_gh, g_h);

    k_init<<<EE / 256, 256>>>(ei, wl[0], wr[0], wl[1], wr[1], wl[2], wr[2]);
    k_scan<<<256, 256>>>();
    k_scatter<<<EE / 256, 256>>>(ei, ei + EE);

    for (int l = 0; l < 3; l++) {
        const float* hsrc = (l == 0) ? x : d_gh;
        k_aggregate<<<NN / 8, 256>>>(hsrc);
        k_gemm<<<NN / 128, 256, SMEM_GEMM>>>(l, bl[l], hsrc, pw[l]);
        k_pool<<<BB, 512>>>(pw[l], KS[l]);
        k_readout<<<BB * 4, 256>>>(l, 1.f / (float)KS[l]);
    }
    k_mlp<<<BB, 128>>>(l1w, l1b, l2w, l2b, l3w, l3b, out);
}